// round 12
// baseline (speedup 1.0000x reference)
#include <cuda_runtime.h>
#include <cstdint>

#define A_ROWS   1160
#define A_BYTES  (A_ROWS * 128)           // 148480
#define B_OFF    A_BYTES
#define B_BYTES  (9 * 32 * 128)           // 36864
#define SMEM_TOTAL (B_OFF + B_BYTES)      // 185344
#define NT 1024

#define SW(o) ((o) ^ (((o) >> 3) & 0x70))

__device__ __forceinline__ uint32_t smem_u32(const void* p) {
    uint32_t a;
    asm("{ .reg .u64 t; cvta.to.shared.u64 t, %1; cvt.u32.u64 %0, t; }" : "=r"(a) : "l"(p));
    return a;
}
__device__ __forceinline__ uint32_t f2bf(float f) {
    uint32_t u = __float_as_uint(f);
    return (u + 0x7FFFu + ((u >> 16) & 1u)) >> 16;
}
__device__ __forceinline__ float bf2f(uint32_t b) { return __uint_as_float(b << 16); }
__device__ __forceinline__ void sts32(uint32_t addr, uint32_t v) {
    asm volatile("st.shared.b32 [%0], %1;" :: "r"(addr), "r"(v) : "memory");
}
__device__ __forceinline__ void ldsm4(uint32_t* r, uint32_t addr) {
    asm volatile("ldmatrix.sync.aligned.m8n8.x4.shared.b16 {%0,%1,%2,%3}, [%4];"
                 : "=r"(r[0]), "=r"(r[1]), "=r"(r[2]), "=r"(r[3]) : "r"(addr));
}
__device__ __forceinline__ void mma16816(float* d, const uint32_t* a,
                                         uint32_t b0, uint32_t b1) {
    asm volatile(
        "mma.sync.aligned.m16n8k16.row.col.f32.bf16.bf16.f32 "
        "{%0,%1,%2,%3}, {%4,%5,%6,%7}, {%8,%9}, {%0,%1,%2,%3};"
        : "+f"(d[0]), "+f"(d[1]), "+f"(d[2]), "+f"(d[3])
        : "r"(a[0]), "r"(a[1]), "r"(a[2]), "r"(a[3]), "r"(b0), "r"(b1));
}

template<int TILES>
__device__ __forceinline__ void gemm_tiles(uint32_t base, int m0base, int lane,
                                           float* o1, float* o2, bool dup) {
    float acc[TILES][4][4];
#pragma unroll
    for (int t = 0; t < TILES; t++)
#pragma unroll
        for (int n = 0; n < 4; n++)
#pragma unroll
            for (int k = 0; k < 4; k++) acc[t][n][k] = 0.0f;

    const int arow_l = lane & 15;
    const int acol_l = (lane >> 4) * 16;
    const int bn_l   = (((lane >> 4) << 3) | (lane & 7)) * 128 + ((lane >> 3) & 1) * 16;

#pragma unroll 1
    for (int tap = 0; tap < 9; tap++) {
        const int sh = (tap / 3) * 34 + (tap % 3);
        int arow_off[TILES];
#pragma unroll
        for (int tt = 0; tt < TILES; tt++)
            arow_off[tt] = (m0base + tt * 16 + sh + arow_l) * 128 + acol_l;
        const int bbase = tap * 4096 + bn_l;

#pragma unroll
        for (int ks = 0; ks < 4; ks++) {
            uint32_t b[8];
            uint32_t ba = base + B_OFF + (uint32_t)SW(bbase + ks * 32);
            ldsm4(b, ba);                 // n 0..15
            ldsm4(b + 4, ba + 2048);      // n 16..31 (lo-correction cols)
#pragma unroll
            for (int tt = 0; tt < TILES; tt++) {
                uint32_t a[4];
                ldsm4(a, base + (uint32_t)SW(arow_off[tt] + ks * 32));
                mma16816(acc[tt][0], a, b[0], b[1]);
                mma16816(acc[tt][1], a, b[2], b[3]);
                mma16816(acc[tt][2], a, b[4], b[5]);
                mma16816(acc[tt][3], a, b[6], b[7]);
            }
        }
    }

    const int n0 = (lane & 3) * 2;
#pragma unroll
    for (int tt = 0; tt < TILES; tt++) {
        const int rlo = m0base + tt * 16 + (lane >> 2);
#pragma unroll
        for (int half = 0; half < 2; half++) {
            const int row = rlo + half * 8;
            const int h = row / 34;
            const int wc = row - h * 34;
            if (wc < 32) {
                const int sp = h * 32 + wc;
#pragma unroll
                for (int nt = 0; nt < 2; nt++) {
#pragma unroll
                    for (int e = 0; e < 2; e++) {
                        float v = acc[tt][nt][half * 2 + e] + acc[tt][nt + 2][half * 2 + e];
                        int n = nt * 8 + n0 + e;
                        o1[(size_t)n * 1024 + sp] = v;
                        if (dup) o2[(size_t)n * 1024 + sp] = v;
                    }
                }
            }
        }
    }
}

__global__ void __launch_bounds__(NT, 1)
fconv_mma(const float* __restrict__ x, const float* __restrict__ w,
          float* __restrict__ out) {
    const int dg  = blockIdx.x;          // 0..8
    const int b   = blockIdx.y;
    const int tid = threadIdx.x;
    const int wid = tid >> 5;
    const int lane = tid & 31;

    extern __shared__ unsigned char smraw[];
    const uint32_t base = smem_u32(smraw);

    // ---- zero pad rows: w in {32,33} for h<32 (64 rows) + rows [1088,1160) ----
    for (int idx = tid; idx < 136 * 8; idx += NT) {
        int row = idx >> 3, c = idx & 7;
        int m = (row < 64) ? ((row >> 1) * 34 + 32 + (row & 1)) : (1088 + row - 64);
        asm volatile("st.shared.v4.b32 [%0], {%1,%1,%1,%1};"
                     :: "r"(base + (uint32_t)(m * 128 + c * 16)), "r"(0u) : "memory");
    }

    // ---- build B: [tap][n][k]; n<16:(w_hi,w_hi), n>=16:(w_lo,0) ----
    for (int idx = tid; idx < 9216; idx += NT) {
        int tap = idx >> 10, rem = idx & 1023;
        int n = rem >> 5, cc = rem & 31;
        int t = tap / 3, j = tap % 3;
        int wbase = cc * 9 + (2 - t) * 3 + (2 - j);
        uint32_t pack;
        if (n < 16) {
            uint32_t hb = f2bf(w[n * 288 + wbase]);
            pack = hb | (hb << 16);
        } else {
            float v = w[(n - 16) * 288 + wbase];
            uint32_t hb = f2bf(v);
            pack = f2bf(v - bf2f(hb));
        }
        sts32(base + B_OFF + tap * 4096 + (uint32_t)SW(n * 128 + cc * 4), pack);
    }

    // ---- build A: u = 0.5*(x[(8dg-cc)%128] + x[(-8dg-cc)%128]) as (hi,lo) pairs ----
    {
        const int m8 = dg * 8;
        const int cc = tid >> 5;                     // 0..31
        const int rq = (tid >> 3) & 3;               // row quarter
        const int w4 = tid & 7;                      // float4 col
        const int ca = (m8 - cc + 128) & 127;
        const int cb = (256 - m8 - cc) & 127;
        const float4* xa = (const float4*)(x + ((size_t)b * 128 + ca) * 1024) + w4;
        const float4* xb = (const float4*)(x + ((size_t)b * 128 + cb) * 1024) + w4;
#pragma unroll 4
        for (int h = rq; h < 32; h += 4) {
            float4 va = xa[h * 8];
            float4 vb = xb[h * 8];
            float uv[4] = {0.5f * (va.x + vb.x), 0.5f * (va.y + vb.y),
                           0.5f * (va.z + vb.z), 0.5f * (va.w + vb.w)};
            int m0 = h * 34 + w4 * 4;
#pragma unroll
            for (int i = 0; i < 4; i++) {
                uint32_t hb = f2bf(uv[i]);
                uint32_t lb = f2bf(uv[i] - bf2f(hb));
                sts32(base + (uint32_t)SW((m0 + i) * 128 + cc * 4), hb | (lb << 16));
            }
        }
    }
    __syncthreads();

    const bool dup = (dg >= 1 && dg <= 7);
    float* o1 = out + ((size_t)b * 256 + dg * 16) * 1024;
    float* o2 = out + ((size_t)b * 256 + (16 - dg) * 16) * 1024;

    // 64 tiles: 2 consecutive per warp (32 warps)
    gemm_tiles<2>(base, wid * 32, lane, o1, o2, dup);
    // tail tiles 64..67 on warps 0..3
    if (wid < 4)
        gemm_tiles<1>(base, 1024 + wid * 16, lane, o1, o2, dup);
}

extern "C" void kernel_launch(void* const* d_in, const int* in_sizes, int n_in,
                              void* d_out, int out_size) {
    const float* x = (const float*)d_in[0];
    const float* w = (const float*)d_in[1];
    float* out = (float*)d_out;

    cudaFuncSetAttribute(fconv_mma,
                         cudaFuncAttributeMaxDynamicSharedMemorySize, SMEM_TOTAL);

    dim3 grid(9, 16);   // 144 CTAs = one wave
    fconv_mma<<<grid, NT, SMEM_TOTAL>>>(x, w, out);
}

// round 15
// speedup vs baseline: 1.1739x; 1.1739x over previous
#include <cuda_runtime.h>
#include <cuda_fp16.h>
#include <cstdint>

#define A_ROWS   1160
#define A_BYTES  (A_ROWS * 128)           // 148480
#define B_OFF    A_BYTES
#define B_BYTES  (9 * 16 * 128)           // 18432
#define SMEM_TOTAL (B_OFF + B_BYTES)      // 166912
#define NT 512

#define SW(o) ((o) ^ (((o) >> 3) & 0x70))

__device__ __forceinline__ uint32_t smem_u32(const void* p) {
    uint32_t a;
    asm("{ .reg .u64 t; cvta.to.shared.u64 t, %1; cvt.u32.u64 %0, t; }" : "=r"(a) : "l"(p));
    return a;
}
__device__ __forceinline__ void sts32(uint32_t addr, uint32_t v) {
    asm volatile("st.shared.b32 [%0], %1;" :: "r"(addr), "r"(v) : "memory");
}
__device__ __forceinline__ void ldsm4(uint32_t* r, uint32_t addr) {
    asm volatile("ldmatrix.sync.aligned.m8n8.x4.shared.b16 {%0,%1,%2,%3}, [%4];"
                 : "=r"(r[0]), "=r"(r[1]), "=r"(r[2]), "=r"(r[3]) : "r"(addr));
}
__device__ __forceinline__ void mma16816(float* d, const uint32_t* a,
                                         uint32_t b0, uint32_t b1) {
    asm volatile(
        "mma.sync.aligned.m16n8k16.row.col.f32.f16.f16.f32 "
        "{%0,%1,%2,%3}, {%4,%5,%6,%7}, {%8,%9}, {%0,%1,%2,%3};"
        : "+f"(d[0]), "+f"(d[1]), "+f"(d[2]), "+f"(d[3])
        : "r"(a[0]), "r"(a[1]), "r"(a[2]), "r"(a[3]), "r"(b0), "r"(b1));
}

template<int TILES>
__device__ __forceinline__ void gemm_tiles(uint32_t base, int m0base, int lane,
                                           float* o1, float* o2, bool dup) {
    float acc[TILES][2][4];
#pragma unroll
    for (int t = 0; t < TILES; t++)
#pragma unroll
        for (int n = 0; n < 2; n++)
#pragma unroll
            for (int k = 0; k < 4; k++) acc[t][n][k] = 0.0f;

    const int arow_l = lane & 15;
    const int acol_l = (lane >> 4) * 16;
    const int bn_l   = (((lane >> 4) << 3) | (lane & 7)) * 128 + ((lane >> 3) & 1) * 16;

#pragma unroll 1
    for (int tap = 0; tap < 9; tap++) {
        const int sh = (tap / 3) * 34 + (tap % 3);
        // precomputed swizzled base addresses; ks advances via XOR (ks<<5)
        uint32_t aa0[TILES];
#pragma unroll
        for (int tt = 0; tt < TILES; tt++)
            aa0[tt] = base + (uint32_t)SW((m0base + tt * 16 + sh + arow_l) * 128 + acol_l);
        const uint32_t ba0 = base + B_OFF + (uint32_t)SW(tap * 2048 + bn_l);

#pragma unroll
        for (int ks = 0; ks < 4; ks++) {
            uint32_t b[4];
            ldsm4(b, ba0 ^ (uint32_t)(ks << 5));
#pragma unroll
            for (int tt = 0; tt < TILES; tt++) {
                uint32_t a[4];
                ldsm4(a, aa0[tt] ^ (uint32_t)(ks << 5));
                mma16816(acc[tt][0], a, b[0], b[1]);
                mma16816(acc[tt][1], a, b[2], b[3]);
            }
        }
    }

    const int n0 = (lane & 3) * 2;
#pragma unroll
    for (int tt = 0; tt < TILES; tt++) {
        const int rlo = m0base + tt * 16 + (lane >> 2);
#pragma unroll
        for (int half = 0; half < 2; half++) {
            const int row = rlo + half * 8;
            const int h = row / 34;
            const int wc = row - h * 34;
            if (wc < 32) {
                const int sp = h * 32 + wc;
#pragma unroll
                for (int nt = 0; nt < 2; nt++) {
#pragma unroll
                    for (int e = 0; e < 2; e++) {
                        float v = acc[tt][nt][half * 2 + e];
                        int n = nt * 8 + n0 + e;
                        o1[(size_t)n * 1024 + sp] = v;
                        if (dup) o2[(size_t)n * 1024 + sp] = v;
                    }
                }
            }
        }
    }
}

__global__ void __launch_bounds__(NT, 1)
fconv_mma(const float* __restrict__ x, const float* __restrict__ w,
          float* __restrict__ out) {
    const int dg  = blockIdx.x;          // 0..8
    const int b   = blockIdx.y;
    const int tid = threadIdx.x;
    const int wid = tid >> 5;
    const int lane = tid & 31;

    extern __shared__ unsigned char smraw[];
    const uint32_t base = smem_u32(smraw);

    // ---- zero pad rows: w in {32,33} for h<32 (64 rows) + rows [1088,1160) ----
    for (int idx = tid; idx < 136 * 8; idx += NT) {
        int row = idx >> 3, c = idx & 7;
        int m = (row < 64) ? ((row >> 1) * 34 + 32 + (row & 1)) : (1088 + row - 64);
        asm volatile("st.shared.v4.b32 [%0], {%1,%1,%1,%1};"
                     :: "r"(base + (uint32_t)(m * 128 + c * 16)), "r"(0u) : "memory");
    }

    // ---- build B: [tap][n<16][k]: (w, w) fp16 pairs ----
    for (int idx = tid; idx < 4608; idx += NT) {
        int tap = idx >> 9, rem = idx & 511;
        int n = rem >> 5, cc = rem & 31;
        int t = tap / 3, j = tap % 3;
        uint32_t h = (uint32_t)__half_as_ushort(
            __float2half_rn(w[n * 288 + cc * 9 + (2 - t) * 3 + (2 - j)]));
        sts32(base + B_OFF + tap * 2048 + (uint32_t)SW(n * 128 + cc * 4),
              h | (h << 16));
    }

    // ---- build A: u = 0.5*(x[(8dg-cc)%128] + x[(-8dg-cc)%128]) as (hi,lo) fp16 pairs ----
    {
        const int m8 = dg * 8;
        const int cc = tid >> 4;                     // 0..31
        const int rh = (tid >> 3) & 1;               // row parity
        const int w4 = tid & 7;                      // float4 col
        const int ca = (m8 - cc + 128) & 127;
        const int cb = (256 - m8 - cc) & 127;
        const float4* xa = (const float4*)(x + ((size_t)b * 128 + ca) * 1024) + w4;
        const float4* xb = (const float4*)(x + ((size_t)b * 128 + cb) * 1024) + w4;
#pragma unroll 4
        for (int h = rh; h < 32; h += 2) {
            float4 va = xa[h * 8];
            float4 vb = xb[h * 8];
            float uv[4] = {0.5f * (va.x + vb.x), 0.5f * (va.y + vb.y),
                           0.5f * (va.z + vb.z), 0.5f * (va.w + vb.w)};
            int m0 = h * 34 + w4 * 4;
#pragma unroll
            for (int i = 0; i < 4; i++) {
                __half hh = __float2half_rn(uv[i]);
                __half hl = __float2half_rn(uv[i] - __half2float(hh));
                sts32(base + (uint32_t)SW((m0 + i) * 128 + cc * 4),
                      (uint32_t)__half_as_ushort(hh) |
                      ((uint32_t)__half_as_ushort(hl) << 16));
            }
        }
    }
    __syncthreads();

    const bool dup = (dg >= 1 && dg <= 7);
    float* o1 = out + ((size_t)b * 256 + dg * 16) * 1024;
    float* o2 = out + ((size_t)b * 256 + (16 - dg) * 16) * 1024;

    // 64 tiles: 4 consecutive per warp (16 warps)
    gemm_tiles<4>(base, wid * 64, lane, o1, o2, dup);
    // tail tiles 64..67 on warps 0..3
    if (wid < 4)
        gemm_tiles<1>(base, 1024 + wid * 16, lane, o1, o2, dup);
}

extern "C" void kernel_launch(void* const* d_in, const int* in_sizes, int n_in,
                              void* d_out, int out_size) {
    const float* x = (const float*)d_in[0];
    const float* w = (const float*)d_in[1];
    float* out = (float*)d_out;

    cudaFuncSetAttribute(fconv_mma,
                         cudaFuncAttributeMaxDynamicSharedMemorySize, SMEM_TOTAL);

    dim3 grid(9, 16);   // 144 CTAs = one wave
    fconv_mma<<<grid, NT, SMEM_TOTAL>>>(x, w, out);
}

// round 16
// speedup vs baseline: 1.6134x; 1.3743x over previous
#include <cuda_runtime.h>
#include <cuda_fp16.h>
#include <cstdint>

#define A_ROWS   1160
#define A_BYTES  (A_ROWS * 64)            // 74240
#define B_OFF    A_BYTES
#define B_BYTES  (9 * 16 * 64)            // 9216
#define SMEM_TOTAL (B_OFF + B_BYTES)      // 83456
#define NT 512

// SW64 swizzle: XOR row bits (7,8) into 16B-chunk bits (4,5)
#define SW(o) ((o) ^ (((o) >> 3) & 0x30))

__device__ __forceinline__ uint32_t smem_u32(const void* p) {
    uint32_t a;
    asm("{ .reg .u64 t; cvta.to.shared.u64 t, %1; cvt.u32.u64 %0, t; }" : "=r"(a) : "l"(p));
    return a;
}
__device__ __forceinline__ void sts16(uint32_t addr, unsigned short v) {
    asm volatile("st.shared.b16 [%0], %1;" :: "r"(addr), "h"(v) : "memory");
}
__device__ __forceinline__ void ldsm4(uint32_t* r, uint32_t addr) {
    asm volatile("ldmatrix.sync.aligned.m8n8.x4.shared.b16 {%0,%1,%2,%3}, [%4];"
                 : "=r"(r[0]), "=r"(r[1]), "=r"(r[2]), "=r"(r[3]) : "r"(addr));
}
__device__ __forceinline__ void mma16816(float* d, const uint32_t* a,
                                         uint32_t b0, uint32_t b1) {
    asm volatile(
        "mma.sync.aligned.m16n8k16.row.col.f32.f16.f16.f32 "
        "{%0,%1,%2,%3}, {%4,%5,%6,%7}, {%8,%9}, {%0,%1,%2,%3};"
        : "+f"(d[0]), "+f"(d[1]), "+f"(d[2]), "+f"(d[3])
        : "r"(a[0]), "r"(a[1]), "r"(a[2]), "r"(a[3]), "r"(b0), "r"(b1));
}

template<int TILES>
__device__ __forceinline__ void gemm_tiles(uint32_t base, int m0base, int lane,
                                           float* o1, float* o2, bool dup) {
    float acc[TILES][2][4];
#pragma unroll
    for (int t = 0; t < TILES; t++)
#pragma unroll
        for (int n = 0; n < 2; n++)
#pragma unroll
            for (int k = 0; k < 4; k++) acc[t][n][k] = 0.0f;

    const int arow_l = lane & 15;
    const int acol_l = (lane >> 4) * 16;
    const int bn_l   = (((lane >> 4) << 3) | (lane & 7)) * 64 + ((lane >> 3) & 1) * 16;

#pragma unroll 1
    for (int tap = 0; tap < 9; tap++) {
        const int sh = (tap / 3) * 34 + (tap % 3);
        uint32_t aa0[TILES];
#pragma unroll
        for (int tt = 0; tt < TILES; tt++)
            aa0[tt] = base + (uint32_t)SW((m0base + tt * 16 + sh + arow_l) * 64 + acol_l);
        const uint32_t ba0 = base + B_OFF + (uint32_t)SW(tap * 1024 + bn_l);

#pragma unroll
        for (int ks = 0; ks < 2; ks++) {
            uint32_t b[4];
            ldsm4(b, ba0 ^ (uint32_t)(ks << 5));
#pragma unroll
            for (int tt = 0; tt < TILES; tt++) {
                uint32_t a[4];
                ldsm4(a, aa0[tt] ^ (uint32_t)(ks << 5));
                mma16816(acc[tt][0], a, b[0], b[1]);
                mma16816(acc[tt][1], a, b[2], b[3]);
            }
        }
    }

    const int n0 = (lane & 3) * 2;
#pragma unroll
    for (int tt = 0; tt < TILES; tt++) {
        const int rlo = m0base + tt * 16 + (lane >> 2);
#pragma unroll
        for (int half = 0; half < 2; half++) {
            const int row = rlo + half * 8;
            const int h = row / 34;
            const int wc = row - h * 34;
            if (wc < 32) {
                const int sp = h * 32 + wc;
#pragma unroll
                for (int nt = 0; nt < 2; nt++) {
#pragma unroll
                    for (int e = 0; e < 2; e++) {
                        float v = acc[tt][nt][half * 2 + e];
                        int n = nt * 8 + n0 + e;
                        o1[(size_t)n * 1024 + sp] = v;
                        if (dup) o2[(size_t)n * 1024 + sp] = v;
                    }
                }
            }
        }
    }
}

__global__ void __launch_bounds__(NT, 1)
fconv_mma(const float* __restrict__ x, const float* __restrict__ w,
          float* __restrict__ out) {
    const int dg  = blockIdx.x;          // 0..8
    const int b   = blockIdx.y;
    const int tid = threadIdx.x;
    const int wid = tid >> 5;
    const int lane = tid & 31;

    extern __shared__ unsigned char smraw[];
    const uint32_t base = smem_u32(smraw);

    // ---- zero pad rows (full 64B rows; SW permutes within-row only) ----
    for (int idx = tid; idx < 136 * 4; idx += NT) {
        int row = idx >> 2, c = idx & 3;
        int m = (row < 64) ? ((row >> 1) * 34 + 32 + (row & 1)) : (1088 + row - 64);
        asm volatile("st.shared.v4.b32 [%0], {%1,%1,%1,%1};"
                     :: "r"(base + (uint32_t)(m * 64 + c * 16)), "r"(0u) : "memory");
    }

    // ---- build B: [tap][n][k=cc] single fp16 ----
    for (int idx = tid; idx < 4608; idx += NT) {
        int tap = idx >> 9, rem = idx & 511;
        int n = rem >> 5, cc = rem & 31;
        int t = tap / 3, j = tap % 3;
        unsigned short h = __half_as_ushort(
            __float2half_rn(w[n * 288 + cc * 9 + (2 - t) * 3 + (2 - j)]));
        sts16(base + B_OFF + tap * 1024 + (uint32_t)SW(n * 64 + cc * 2), h);
    }

    // ---- build A: u = 0.5*(x[(8dg-cc)%128] + x[(-8dg-cc)%128]) single fp16 ----
    {
        const int m8 = dg * 8;
        const int cc = tid >> 4;                     // 0..31
        const int rh = (tid >> 3) & 1;               // row parity
        const int w4 = tid & 7;                      // float4 col
        const int ca = (m8 - cc + 128) & 127;
        const int cb = (256 - m8 - cc) & 127;
        const float4* xa = (const float4*)(x + ((size_t)b * 128 + ca) * 1024) + w4;
        const float4* xb = (const float4*)(x + ((size_t)b * 128 + cb) * 1024) + w4;
#pragma unroll 4
        for (int h = rh; h < 32; h += 2) {
            float4 va = xa[h * 8];
            float4 vb = xb[h * 8];
            float uv[4] = {0.5f * (va.x + vb.x), 0.5f * (va.y + vb.y),
                           0.5f * (va.z + vb.z), 0.5f * (va.w + vb.w)};
            int m0 = h * 34 + w4 * 4;
#pragma unroll
            for (int i = 0; i < 4; i++) {
                sts16(base + (uint32_t)SW((m0 + i) * 64 + cc * 2),
                      __half_as_ushort(__float2half_rn(uv[i])));
            }
        }
    }
    __syncthreads();

    const bool dup = (dg >= 1 && dg <= 7);
    float* o1 = out + ((size_t)b * 256 + dg * 16) * 1024;
    float* o2 = out + ((size_t)b * 256 + (16 - dg) * 16) * 1024;

    // 64 tiles: 4 consecutive per warp (16 warps)
    gemm_tiles<4>(base, wid * 64, lane, o1, o2, dup);
    // tail tiles 64..67 on warps 0..3
    if (wid < 4)
        gemm_tiles<1>(base, 1024 + wid * 16, lane, o1, o2, dup);
}

extern "C" void kernel_launch(void* const* d_in, const int* in_sizes, int n_in,
                              void* d_out, int out_size) {
    const float* x = (const float*)d_in[0];
    const float* w = (const float*)d_in[1];
    float* out = (float*)d_out;

    cudaFuncSetAttribute(fconv_mma,
                         cudaFuncAttributeMaxDynamicSharedMemorySize, SMEM_TOTAL);

    dim3 grid(9, 16);   // 144 CTAs = one wave
    fconv_mma<<<grid, NT, SMEM_TOTAL>>>(x, w, out);
}

// round 17
// speedup vs baseline: 1.7159x; 1.0636x over previous
#include <cuda_runtime.h>
#include <cuda_fp16.h>
#include <cstdint>

#define A_ROWS   1160
#define A_BYTES  (A_ROWS * 64)            // 74240
#define B_OFF    A_BYTES
#define B_BYTES  (9 * 16 * 64)            // 9216
#define SMEM_TOTAL (B_OFF + B_BYTES)      // 83456
#define NT 512
#define STAGE_PS 1028                     // staging pitch in floats (mod 32 = 4)

// SW64 swizzle: XOR row bits into 16B-chunk bits (4,5)
#define SW(o) ((o) ^ (((o) >> 3) & 0x30))

__device__ __forceinline__ uint32_t smem_u32(const void* p) {
    uint32_t a;
    asm("{ .reg .u64 t; cvta.to.shared.u64 t, %1; cvt.u32.u64 %0, t; }" : "=r"(a) : "l"(p));
    return a;
}
__device__ __forceinline__ void sts16(uint32_t addr, unsigned short v) {
    asm volatile("st.shared.b16 [%0], %1;" :: "r"(addr), "h"(v) : "memory");
}
__device__ __forceinline__ void ldsm4(uint32_t* r, uint32_t addr) {
    asm volatile("ldmatrix.sync.aligned.m8n8.x4.shared.b16 {%0,%1,%2,%3}, [%4];"
                 : "=r"(r[0]), "=r"(r[1]), "=r"(r[2]), "=r"(r[3]) : "r"(addr));
}
__device__ __forceinline__ void mma16816(float* d, const uint32_t* a,
                                         uint32_t b0, uint32_t b1) {
    asm volatile(
        "mma.sync.aligned.m16n8k16.row.col.f32.f16.f16.f32 "
        "{%0,%1,%2,%3}, {%4,%5,%6,%7}, {%8,%9}, {%0,%1,%2,%3};"
        : "+f"(d[0]), "+f"(d[1]), "+f"(d[2]), "+f"(d[3])
        : "r"(a[0]), "r"(a[1]), "r"(a[2]), "r"(a[3]), "r"(b0), "r"(b1));
}

template<int TILES>
__device__ __forceinline__ void gemm_compute(uint32_t base, int m0base, int lane,
                                             float (*acc)[2][4]) {
#pragma unroll
    for (int t = 0; t < TILES; t++)
#pragma unroll
        for (int n = 0; n < 2; n++)
#pragma unroll
            for (int k = 0; k < 4; k++) acc[t][n][k] = 0.0f;

    const int arow_l = lane & 15;
    const int acol_l = (lane >> 4) * 16;
    const int bn_l   = (((lane >> 4) << 3) | (lane & 7)) * 64 + ((lane >> 3) & 1) * 16;

#pragma unroll 1
    for (int tap = 0; tap < 9; tap++) {
        const int sh = (tap / 3) * 34 + (tap % 3);
        uint32_t aa0[TILES];
#pragma unroll
        for (int tt = 0; tt < TILES; tt++)
            aa0[tt] = base + (uint32_t)SW((m0base + tt * 16 + sh + arow_l) * 64 + acol_l);
        const uint32_t ba0 = base + B_OFF + (uint32_t)SW(tap * 1024 + bn_l);

#pragma unroll
        for (int ks = 0; ks < 2; ks++) {
            uint32_t b[4];
            ldsm4(b, ba0 ^ (uint32_t)(ks << 5));
#pragma unroll
            for (int tt = 0; tt < TILES; tt++) {
                uint32_t a[4];
                ldsm4(a, aa0[tt] ^ (uint32_t)(ks << 5));
                mma16816(acc[tt][0], a, b[0], b[1]);
                mma16816(acc[tt][1], a, b[2], b[3]);
            }
        }
    }
}

template<int TILES>
__device__ __forceinline__ void stage_store(float* stage, int m0base, int lane,
                                            const float (*acc)[2][4]) {
    const int n0 = (lane & 3) * 2;
#pragma unroll
    for (int tt = 0; tt < TILES; tt++) {
        const int rlo = m0base + tt * 16 + (lane >> 2);
#pragma unroll
        for (int half = 0; half < 2; half++) {
            const int row = rlo + half * 8;
            const int h = row / 34;
            const int wc = row - h * 34;
            if (wc < 32) {
                const int sp = h * 32 + wc;
#pragma unroll
                for (int nt = 0; nt < 2; nt++) {
#pragma unroll
                    for (int e = 0; e < 2; e++)
                        stage[(nt * 8 + n0 + e) * STAGE_PS + sp] =
                            acc[tt][nt][half * 2 + e];
                }
            }
        }
    }
}

__global__ void __launch_bounds__(NT, 1)
fconv_mma(const float* __restrict__ x, const float* __restrict__ w,
          float* __restrict__ out) {
    const int dg  = blockIdx.x;          // 0..8
    const int b   = blockIdx.y;
    const int tid = threadIdx.x;
    const int wid = tid >> 5;
    const int lane = tid & 31;

    extern __shared__ unsigned char smraw[];
    const uint32_t base = smem_u32(smraw);
    float* stage = (float*)smraw;        // reuses A rows 0..1027 (tail uses >=1088)

    // ---- zero pad rows ----
    for (int idx = tid; idx < 136 * 4; idx += NT) {
        int row = idx >> 2, c = idx & 3;
        int m = (row < 64) ? ((row >> 1) * 34 + 32 + (row & 1)) : (1088 + row - 64);
        asm volatile("st.shared.v4.b32 [%0], {%1,%1,%1,%1};"
                     :: "r"(base + (uint32_t)(m * 64 + c * 16)), "r"(0u) : "memory");
    }

    // ---- build B: [tap][n][k=cc] single fp16 ----
    for (int idx = tid; idx < 4608; idx += NT) {
        int tap = idx >> 9, rem = idx & 511;
        int n = rem >> 5, cc = rem & 31;
        int t = tap / 3, j = tap % 3;
        unsigned short h = __half_as_ushort(
            __float2half_rn(w[n * 288 + cc * 9 + (2 - t) * 3 + (2 - j)]));
        sts16(base + B_OFF + tap * 1024 + (uint32_t)SW(n * 64 + cc * 2), h);
    }

    // ---- build A: u = 0.5*(x[(8dg-cc)%128] + x[(-8dg-cc)%128]) single fp16 ----
    {
        const int m8 = dg * 8;
        const int cc = tid >> 4;                     // 0..31
        const int rh = (tid >> 3) & 1;               // row parity
        const int w4 = tid & 7;                      // float4 col
        const int ca = (m8 - cc + 128) & 127;
        const int cb = (256 - m8 - cc) & 127;
        const float4* xa = (const float4*)(x + ((size_t)b * 128 + ca) * 1024) + w4;
        const float4* xb = (const float4*)(x + ((size_t)b * 128 + cb) * 1024) + w4;
#pragma unroll 4
        for (int h = rh; h < 32; h += 2) {
            float4 va = xa[h * 8];
            float4 vb = xb[h * 8];
            float uv[4] = {0.5f * (va.x + vb.x), 0.5f * (va.y + vb.y),
                           0.5f * (va.z + vb.z), 0.5f * (va.w + vb.w)};
            int m0 = h * 34 + w4 * 4;
#pragma unroll
            for (int i = 0; i < 4; i++) {
                sts16(base + (uint32_t)SW((m0 + i) * 64 + cc * 2),
                      __half_as_ushort(__float2half_rn(uv[i])));
            }
        }
    }
    __syncthreads();

    // ---- compute (acc stays in regs) ----
    float accA[4][2][4];
    gemm_compute<4>(base, wid * 64, lane, accA);
    float accB[1][2][4];
    if (wid < 4) gemm_compute<1>(base, 1024 + wid * 16, lane, accB);

    __syncthreads();   // everyone done reading A rows < 1088

    // ---- scatter acc into staging [n][sp], pitch 1028 (conflict-free) ----
    stage_store<4>(stage, wid * 64, lane, accA);
    if (wid < 4) stage_store<1>(stage, 1024 + wid * 16, lane, accB);

    __syncthreads();

    // ---- coalesced float4 write-out (primary + mirror) ----
    const bool dup = (dg >= 1 && dg <= 7);
    float* o1 = out + ((size_t)b * 256 + dg * 16) * 1024;
    float* o2 = out + ((size_t)b * 256 + (16 - dg) * 16) * 1024;

    for (int i = tid; i < 4096; i += NT) {
        int n = i >> 8;
        int sp4 = (i & 255) << 2;
        float4 v = *(const float4*)(stage + n * STAGE_PS + sp4);
        *(float4*)(o1 + (size_t)n * 1024 + sp4) = v;
        if (dup) *(float4*)(o2 + (size_t)n * 1024 + sp4) = v;
    }
}

extern "C" void kernel_launch(void* const* d_in, const int* in_sizes, int n_in,
                              void* d_out, int out_size) {
    const float* x = (const float*)d_in[0];
    const float* w = (const float*)d_in[1];
    float* out = (float*)d_out;

    cudaFuncSetAttribute(fconv_mma,
                         cudaFuncAttributeMaxDynamicSharedMemorySize, SMEM_TOTAL);

    dim3 grid(9, 16);   // 144 CTAs = one wave
    fconv_mma<<<grid, NT, SMEM_TOTAL>>>(x, w, out);
}